// round 13
// baseline (speedup 1.0000x reference)
#include <cuda_runtime.h>
#include <cuda_fp16.h>
#include <cstdint>

// ---------------------------------------------------------------------------
// EfficientAdditiveAttention — round 13 (third submission of the R11 change
// set; rounds 11/12 hit broker/container infra failures before the kernel
// was ever compiled or run). GEMM cores byte-identical to the 520us R10
// winner; qk_gemm at launch slot #4 (empirical ncu capture position);
// finalize_g folded into build_wpfbt; 9 launches total.
//
//   q = x@Wq + bq ; k = x@Wk + bk
//   qw = (q/||q||).w_g ; kn = k/||k||
//   S_b = sum qw^2 ; Gacc_b = sum qw*q ; G_b = SCALE*Gacc/max(SCALE*sqrt(S),EPS)
//   out = q@Wf + kn@(diag(G_b)·Wp@Wf) + (bp@Wf + bf)
// ---------------------------------------------------------------------------

#define BATCH   16
#define SEQ     4096
#define HDIM    512
#define TDIM    256
#define MTOT    (BATCH * SEQ)
#define EPS_F   1e-12f
#define SCALE_F 0.044194173824159216f

// ---------------- scratch (device globals; no runtime alloc) ---------------
__device__ __align__(16) __half g_Xh[(size_t)MTOT * HDIM];     // x in fp16
__device__ __align__(16) __half g_Qh[(size_t)MTOT * HDIM];     // q fp16
__device__ __align__(16) __half g_Kh[(size_t)MTOT * HDIM];     // k -> kn fp16
__device__ __align__(16) __half g_WqT[HDIM * HDIM];            // Wq^T [n][k]
__device__ __align__(16) __half g_WkT[HDIM * HDIM];
__device__ __align__(16) __half g_WfT[TDIM * HDIM];            // Wf^T [256][512]
__device__ __align__(16) __half g_WpfbT[(size_t)BATCH * TDIM * HDIM]; // (diag(G)Wpf)^T
__device__ float g_Wpf[HDIM * TDIM];                           // Wp@Wf fp32
__device__ float g_cpf[TDIM];
__device__ float g_Gacc[BATCH * HDIM];
__device__ float g_S[BATCH];

// ---------------------------- helpers --------------------------------------
__device__ __forceinline__ uint32_t smem_u32(const void* p) {
    uint32_t a;
    asm("{ .reg .u64 t; cvta.to.shared.u64 t, %1; cvt.u32.u64 %0, t; }" : "=r"(a) : "l"(p));
    return a;
}

#define CP_ASYNC16(dst, src) \
    asm volatile("cp.async.cg.shared.global [%0], [%1], 16;" :: "r"(dst), "l"(src) : "memory")
#define CP_COMMIT() asm volatile("cp.async.commit_group;" ::: "memory")
#define CP_WAIT1()  asm volatile("cp.async.wait_group 1;" ::: "memory")

__device__ __forceinline__ void mma_f16(float c[4], const uint32_t a[4], const uint32_t b[2]) {
    asm volatile(
        "mma.sync.aligned.m16n8k16.row.col.f32.f16.f16.f32 "
        "{%0,%1,%2,%3}, {%4,%5,%6,%7}, {%8,%9}, {%0,%1,%2,%3};\n"
        : "+f"(c[0]), "+f"(c[1]), "+f"(c[2]), "+f"(c[3])
        : "r"(a[0]), "r"(a[1]), "r"(a[2]), "r"(a[3]), "r"(b[0]), "r"(b[1]));
}

__device__ __forceinline__ void ldsm4(uint32_t& r0, uint32_t& r1, uint32_t& r2, uint32_t& r3,
                                      uint32_t addr) {
    asm volatile("ldmatrix.sync.aligned.m8n8.x4.shared.b16 {%0,%1,%2,%3}, [%4];"
                 : "=r"(r0), "=r"(r1), "=r"(r2), "=r"(r3) : "r"(addr));
}

// stage geometry: BK=64. A tile 128x64 ld=72; W tile 128x64 ld=72.
#define LDT 72
#define A_BYTES (128 * LDT * 2)                 // 18432
#define W_BYTES (128 * LDT * 2)                 // 18432
#define STAGE_BYTES (A_BYTES + W_BYTES)         // 36864
#define NSTG 3
#define SMEM_DYN (NSTG * STAGE_BYTES)           // 110592 -> 2 CTAs/SM

// load one (A 128x64, W 128x64) chunk of halves into a stage
__device__ __forceinline__ void load_tile(uint32_t stA, const __half* __restrict__ A,
                                          const __half* __restrict__ Wt,
                                          int r0, int n0, int k0, int tid) {
    uint32_t stW = stA + A_BYTES;
#pragma unroll
    for (int it = 0; it < 4; ++it) {            // A: 128 rows x 8 granules = 1024
        int u = tid + it * 256;
        int row = u >> 3, c = u & 7;
        CP_ASYNC16(stA + (uint32_t)(row * LDT * 2 + c * 16),
                   A + (size_t)(r0 + row) * HDIM + k0 + c * 8);
    }
#pragma unroll
    for (int it = 0; it < 4; ++it) {            // W: 128 rows x 8 granules = 1024
        int u = tid + it * 256;
        int row = u >> 3, c = u & 7;
        CP_ASYNC16(stW + (uint32_t)(row * LDT * 2 + c * 16),
                   Wt + (size_t)(n0 + row) * HDIM + k0 + c * 8);
    }
}

// one BK=64 chunk: 4 k16 steps, warp tile 64x32, ldmatrix.x4 feeds
__device__ __forceinline__ void compute_chunk(uint32_t aBase, uint32_t bBase,
                                              float acc[4][4][4]) {
#pragma unroll
    for (int ks = 0; ks < 4; ++ks) {
        uint32_t af[4][4], bw[4][2];
#pragma unroll
        for (int mf = 0; mf < 4; ++mf)
            ldsm4(af[mf][0], af[mf][1], af[mf][2], af[mf][3],
                  aBase + (uint32_t)((mf * 16 * LDT + ks * 16) * 2));
#pragma unroll
        for (int np = 0; np < 2; ++np)
            ldsm4(bw[2 * np][0], bw[2 * np][1], bw[2 * np + 1][0], bw[2 * np + 1][1],
                  bBase + (uint32_t)((np * 16 * LDT + ks * 16) * 2));
#pragma unroll
        for (int mf = 0; mf < 4; ++mf)
#pragma unroll
            for (int nf = 0; nf < 4; ++nf) mma_f16(acc[mf][nf], af[mf], bw[nf]);
    }
}

// ---------------------------------------------------------------------------
// small kernels
// ---------------------------------------------------------------------------
__global__ void conv_x_kernel(const float* __restrict__ x) {
    size_t gtid = blockIdx.x * blockDim.x + threadIdx.x;
    if (gtid < BATCH * HDIM) g_Gacc[gtid] = 0.0f;      // fold stats zeroing here
    if (gtid < BATCH) g_S[gtid] = 0.0f;
    size_t n4 = (size_t)MTOT * HDIM / 4;
    __half2* dst = reinterpret_cast<__half2*>(g_Xh);
    for (size_t i = gtid; i < n4; i += (size_t)gridDim.x * blockDim.x) {
        float4 v = reinterpret_cast<const float4*>(x)[i];
        dst[2 * i]     = __floats2half2_rn(v.x, v.y);
        dst[2 * i + 1] = __floats2half2_rn(v.z, v.w);
    }
}

// dst[n][k] = half(src[k][n]); src rows=K, cols=N (n contiguous)
__global__ void transpose_h_kernel(const float* __restrict__ src, __half* __restrict__ dst,
                                   int rows, int cols) {
    __shared__ float t[32][33];
    int x0 = blockIdx.x * 32, y0 = blockIdx.y * 32;
    int tx = threadIdx.x, ty = threadIdx.y;
#pragma unroll
    for (int i = 0; i < 4; ++i)
        t[ty + 8 * i][tx] = src[(size_t)(y0 + ty + 8 * i) * cols + x0 + tx];
    __syncthreads();
#pragma unroll
    for (int i = 0; i < 4; ++i)
        dst[(size_t)(x0 + ty + 8 * i) * rows + y0 + tx] = __float2half_rn(t[tx][ty + 8 * i]);
}

__global__ void prep_kernel(const float* __restrict__ Wp, const float* __restrict__ Wf,
                            const float* __restrict__ bp, const float* __restrict__ bf) {
    int j = threadIdx.x;
    if (blockIdx.x < 32) {
        __shared__ float Wp_s[16][512];
        int i0 = blockIdx.x * 16;
        for (int i = threadIdx.x; i < 16 * 512; i += 256)
            Wp_s[i >> 9][i & 511] = Wp[(size_t)(i0 + (i >> 9)) * 512 + (i & 511)];
        __syncthreads();
        float acc[16];
#pragma unroll
        for (int i = 0; i < 16; ++i) acc[i] = 0.0f;
        for (int k = 0; k < 512; ++k) {
            float wf = Wf[(size_t)k * TDIM + j];
#pragma unroll
            for (int i = 0; i < 16; ++i) acc[i] += Wp_s[i][k] * wf;
        }
#pragma unroll
        for (int i = 0; i < 16; ++i) g_Wpf[(size_t)(i0 + i) * TDIM + j] = acc[i];
    } else {
        __shared__ float bp_s[512];
        for (int i = threadIdx.x; i < 512; i += 256) bp_s[i] = bp[i];
        __syncthreads();
        float a = bf[j];
        for (int k = 0; k < 512; ++k) a += bp_s[k] * Wf[(size_t)k * TDIM + j];
        g_cpf[j] = a;
    }
}

// WpfbT[b][n][k] = half(G[b][k] * Wpf[k][n]), G computed inline from Gacc/S.
// grid(256,16) block 512
__global__ void build_wpfbt_kernel() {
    int n = blockIdx.x, b = blockIdx.y, k = threadIdx.x;
    float denom = fmaxf(SCALE_F * sqrtf(g_S[b]), EPS_F);
    float gk = SCALE_F * g_Gacc[b * HDIM + k] / denom;
    g_WpfbT[((size_t)b * TDIM + n) * HDIM + k] =
        __float2half_rn(gk * g_Wpf[(size_t)k * TDIM + n]);
}

// ---------------------------------------------------------------------------
// rowwise: norms + qw + kn(in place, half) + per-batch reductions (half I/O)
// ---------------------------------------------------------------------------
__global__ void rowwise_kernel(const float* __restrict__ wg) {
    __shared__ float wg_s[512];
    __shared__ float Gs[8][512];
    __shared__ float Sq[8];
    const int tid = threadIdx.x, warp = tid >> 5, lane = tid & 31;
    const int r0 = blockIdx.x * 128;
    const int b = r0 >> 12;

    for (int i = tid; i < 512; i += 256) wg_s[i] = wg[i];
    for (int i = tid; i < 8 * 512; i += 256) (&Gs[0][0])[i] = 0.0f;
    __syncthreads();

    float qw2 = 0.0f;
    for (int rt = 0; rt < 16; ++rt) {
        int r = r0 + rt * 8 + warp;
        const __half2* qr = reinterpret_cast<const __half2*>(g_Qh + (size_t)r * HDIM);
        __half2* kr = reinterpret_cast<__half2*>(g_Kh + (size_t)r * HDIM);
        float2 q[8], k[8];
        float sq = 0.0f, sg = 0.0f, sk = 0.0f;
#pragma unroll
        for (int t = 0; t < 8; ++t) {
            int j2 = lane + 32 * t;
            q[t] = __half22float2(qr[j2]);
            k[t] = __half22float2(kr[j2]);
            sq += q[t].x * q[t].x + q[t].y * q[t].y;
            sk += k[t].x * k[t].x + k[t].y * k[t].y;
            sg += q[t].x * wg_s[2 * j2] + q[t].y * wg_s[2 * j2 + 1];
        }
#pragma unroll
        for (int o = 16; o; o >>= 1) {
            sq += __shfl_xor_sync(0xffffffffu, sq, o);
            sg += __shfl_xor_sync(0xffffffffu, sg, o);
            sk += __shfl_xor_sync(0xffffffffu, sk, o);
        }
        float dq = fmaxf(sqrtf(sq), EPS_F);
        float dk = fmaxf(sqrtf(sk), EPS_F);
        float qw = sg / dq;
        float rk = 1.0f / dk;
        qw2 += qw * qw;
#pragma unroll
        for (int t = 0; t < 8; ++t) {
            int j2 = lane + 32 * t;
            kr[j2] = __floats2half2_rn(k[t].x * rk, k[t].y * rk);
            Gs[warp][2 * j2]     += qw * q[t].x;
            Gs[warp][2 * j2 + 1] += qw * q[t].y;
        }
    }
    if (lane == 0) Sq[warp] = qw2;
    __syncthreads();

    for (int j = tid; j < 512; j += 256) {
        float s = 0.0f;
#pragma unroll
        for (int w = 0; w < 8; ++w) s += Gs[w][j];
        atomicAdd(&g_Gacc[b * HDIM + j], s);
    }
    if (tid == 0) {
        float s = 0.0f;
#pragma unroll
        for (int w = 0; w < 8; ++w) s += Sq[w];
        atomicAdd(&g_S[b], s);
    }
}

// ---------------------------------------------------------------------------
// Fused Q/K GEMM (fp16): grid (8, 512). bx<4 -> Q (n0=bx*128), else K.
// CTA 128x128, warp 64x32, BK=64, 3-stage cp.async, 2 CTAs/SM.
// ---------------------------------------------------------------------------
__global__ __launch_bounds__(256, 2)
void qk_gemm_kernel(const float* __restrict__ bq, const float* __restrict__ bk) {
    extern __shared__ char sm_raw[];
    const int bx = blockIdx.x;
    const bool isQ = (bx < 4);
    const __half* Wt = isQ ? g_WqT : g_WkT;
    const float* bias = isQ ? bq : bk;
    __half* C = isQ ? g_Qh : g_Kh;
    const int n0 = (bx & 3) * 128;
    const int r0 = blockIdx.y * 128;
    const int tid = threadIdx.x, warp = tid >> 5, lane = tid & 31;
    const int wm = warp >> 2, wn = warp & 3, g = lane >> 2, tg = lane & 3;

    uint32_t smBase = smem_u32(sm_raw);
    const uint32_t aOff = (uint32_t)(((wm * 64 + (lane & 15)) * LDT + ((lane >> 4) * 8)) * 2);
    const uint32_t bOff = (uint32_t)(A_BYTES +
        ((wn * 32 + ((lane >> 4) * 8) + (lane & 7)) * LDT + (((lane >> 3) & 1) * 8)) * 2);

    float acc[4][4][4];
#pragma unroll
    for (int a = 0; a < 4; ++a)
#pragma unroll
        for (int b2 = 0; b2 < 4; ++b2)
#pragma unroll
            for (int c = 0; c < 4; ++c) acc[a][b2][c] = 0.0f;

    load_tile(smBase + 0 * STAGE_BYTES, g_Xh, Wt, r0, n0, 0, tid);  CP_COMMIT();
    load_tile(smBase + 1 * STAGE_BYTES, g_Xh, Wt, r0, n0, 64, tid); CP_COMMIT();

    const int TOT = 8;                                   // K=512 / BK=64
    for (int c = 0; c < TOT; ++c) {
        CP_WAIT1();                                      // chunk c resident
        __syncthreads();                                 // all warps done with c-1
        if (c + 2 < TOT) {
            load_tile(smBase + (uint32_t)((c + 2) % NSTG) * STAGE_BYTES, g_Xh, Wt,
                      r0, n0, (c + 2) * 64, tid);
            CP_COMMIT();
        }
        uint32_t stage = smBase + (uint32_t)(c % NSTG) * STAGE_BYTES;
        compute_chunk(stage + aOff, stage + bOff, acc);
    }

#pragma unroll
    for (int mf = 0; mf < 4; ++mf) {
#pragma unroll
        for (int nf = 0; nf < 4; ++nf) {
            int row = r0 + wm * 64 + mf * 16 + g;
            int col = n0 + wn * 32 + nf * 8 + tg * 2;
            float b0v = bias[col], b1v = bias[col + 1];
            *reinterpret_cast<__half2*>(&C[(size_t)row * HDIM + col]) =
                __floats2half2_rn(acc[mf][nf][0] + b0v, acc[mf][nf][1] + b1v);
            *reinterpret_cast<__half2*>(&C[(size_t)(row + 8) * HDIM + col]) =
                __floats2half2_rn(acc[mf][nf][2] + b0v, acc[mf][nf][3] + b1v);
        }
    }
}

// ---------------------------------------------------------------------------
// Final GEMM (fp16): out = Q@Wf + KN@Wpfb[batch] + cpf.  grid (2, 512).
// 2 passes of K=512 (8 BK=64 chunks each) into one 128x128 tile.
// ---------------------------------------------------------------------------
__global__ __launch_bounds__(256, 2)
void final_gemm_kernel(float* __restrict__ out) {
    extern __shared__ char sm_raw[];
    const int n0 = blockIdx.x * 128;
    const int r0 = blockIdx.y * 128;
    const int batch = r0 >> 12;
    const __half* W1 = g_WpfbT + (size_t)batch * TDIM * HDIM;
    const int tid = threadIdx.x, warp = tid >> 5, lane = tid & 31;
    const int wm = warp >> 2, wn = warp & 3, g = lane >> 2, tg = lane & 3;

    uint32_t smBase = smem_u32(sm_raw);
    const uint32_t aOff = (uint32_t)(((wm * 64 + (lane & 15)) * LDT + ((lane >> 4) * 8)) * 2);
    const uint32_t bOff = (uint32_t)(A_BYTES +
        ((wn * 32 + ((lane >> 4) * 8) + (lane & 7)) * LDT + (((lane >> 3) & 1) * 8)) * 2);

    float acc[4][4][4];
#pragma unroll
    for (int a = 0; a < 4; ++a)
#pragma unroll
        for (int b2 = 0; b2 < 4; ++b2)
#pragma unroll
            for (int c = 0; c < 4; ++c) acc[a][b2][c] = 0.0f;

    auto issue = [&](int c) {
        int pass = c >> 3, k0 = (c & 7) * 64;
        load_tile(smBase + (uint32_t)(c % NSTG) * STAGE_BYTES,
                  pass ? g_Kh : g_Qh, pass ? W1 : g_WfT, r0, n0, k0, tid);
    };

    issue(0); CP_COMMIT();
    issue(1); CP_COMMIT();

    const int TOT = 16;
    for (int c = 0; c < TOT; ++c) {
        CP_WAIT1();
        __syncthreads();
        if (c + 2 < TOT) { issue(c + 2); CP_COMMIT(); }
        uint32_t stage = smBase + (uint32_t)(c % NSTG) * STAGE_BYTES;
        compute_chunk(stage + aOff, stage + bOff, acc);
    }

#pragma unroll
    for (int mf = 0; mf < 4; ++mf) {
#pragma unroll
        for (int nf = 0; nf < 4; ++nf) {
            int row = r0 + wm * 64 + mf * 16 + g;
            int col = n0 + wn * 32 + nf * 8 + tg * 2;
            float b0v = g_cpf[col], b1v = g_cpf[col + 1];
            *reinterpret_cast<float2*>(&out[(size_t)row * TDIM + col]) =
                make_float2(acc[mf][nf][0] + b0v, acc[mf][nf][1] + b1v);
            *reinterpret_cast<float2*>(&out[(size_t)(row + 8) * TDIM + col]) =
                make_float2(acc[mf][nf][2] + b0v, acc[mf][nf][3] + b1v);
        }
    }
}

// ---------------------------------------------------------------------------
extern "C" void kernel_launch(void* const* d_in, const int* in_sizes, int n_in,
                              void* d_out, int out_size) {
    const float* x  = (const float*)d_in[0];
    const float* Wq = (const float*)d_in[1];
    const float* bq = (const float*)d_in[2];
    const float* Wk = (const float*)d_in[3];
    const float* bk = (const float*)d_in[4];
    const float* wg = (const float*)d_in[5];
    const float* Wp = (const float*)d_in[6];
    const float* bp = (const float*)d_in[7];
    const float* Wf = (const float*)d_in[8];
    const float* bf = (const float*)d_in[9];
    float* out = (float*)d_out;

    cudaFuncSetAttribute(qk_gemm_kernel, cudaFuncAttributeMaxDynamicSharedMemorySize, SMEM_DYN);
    cudaFuncSetAttribute(final_gemm_kernel, cudaFuncAttributeMaxDynamicSharedMemorySize, SMEM_DYN);

    __half* pWqT; cudaGetSymbolAddress((void**)&pWqT, g_WqT);
    __half* pWkT; cudaGetSymbolAddress((void**)&pWkT, g_WkT);
    __half* pWfT; cudaGetSymbolAddress((void**)&pWfT, g_WfT);

    conv_x_kernel<<<2048, 256>>>(x);                                        // 1 (+ stats zero)
    transpose_h_kernel<<<dim3(16, 16), dim3(32, 8)>>>(Wq, pWqT, 512, 512);  // 2
    transpose_h_kernel<<<dim3(16, 16), dim3(32, 8)>>>(Wk, pWkT, 512, 512);  // 3
    qk_gemm_kernel<<<dim3(8, 512), 256, SMEM_DYN>>>(bq, bk);                // 4 <- ncu slot
    transpose_h_kernel<<<dim3(8, 16), dim3(32, 8)>>>(Wf, pWfT, 512, 256);   // 5
    prep_kernel<<<33, 256>>>(Wp, Wf, bp, bf);                               // 6
    rowwise_kernel<<<512, 256>>>(wg);                                       // 7
    build_wpfbt_kernel<<<dim3(256, 16), 512>>>();                           // 8 (G inline)
    final_gemm_kernel<<<dim3(2, 512), 256, SMEM_DYN>>>(out);                // 9
}

// round 16
// speedup vs baseline: 1.0117x; 1.0117x over previous
#include <cuda_runtime.h>
#include <cuda_fp16.h>
#include <cstdint>

// ---------------------------------------------------------------------------
// EfficientAdditiveAttention, round 16.
// Functional content equals the R14/R15 submission (which never reached the
// GPU: broker container failures both times). Header rewritten to change the
// source hash, mirroring the R13 workaround for the same failure signature.
//
// Pipeline overview:
//   stage A: conv x -> fp16, zero per-batch stats
//   stage B: transpose Wq/Wk/Wf to [n][k] fp16 (one launch, z-indexed)
//   stage C: prep  Wpf = Wp@Wf, cpf = bp@Wf + bf
//   stage D: qk GEMM (fused Q and K over grid.x)         <- profiler slot 4
//   stage E: rowwise norms, qw, kn in place, batch stats
//   stage F: WpfbT[b] = (diag(G_b) Wpf)^T in fp16, G from stats inline
//   stage G: final GEMM  out = Q@WfT + KN@WpfbT[b] + cpf
//
// GEMM core: fp16 mma.m16n8k16, CTA tile 128x128, warp tile 64x32, BK=64,
// 3-stage cp.async ring (36KB/stage, 2 CTAs/SM), ldmatrix.x4 feeds that are
// SOFTWARE-PIPELINED: A fragments double-buffered per (ks,mf) step and B
// fragments double-buffered per ks, so LDSM issue slots interleave with the
// MMA stream instead of alternating in bursts (R13 ncu showed tensor=54.9%
// vs L1=58.0%, i.e. the two pipes taking turns).
// ---------------------------------------------------------------------------

#define BATCH   16
#define SEQ     4096
#define HDIM    512
#define TDIM    256
#define MTOT    (BATCH * SEQ)
#define EPS_F   1e-12f
#define SCALE_F 0.044194173824159216f

// ---------------- scratch (device globals; no runtime alloc) ---------------
__device__ __align__(16) __half g_Xh[(size_t)MTOT * HDIM];
__device__ __align__(16) __half g_Qh[(size_t)MTOT * HDIM];
__device__ __align__(16) __half g_Kh[(size_t)MTOT * HDIM];
__device__ __align__(16) __half g_WqT[HDIM * HDIM];
__device__ __align__(16) __half g_WkT[HDIM * HDIM];
__device__ __align__(16) __half g_WfT[TDIM * HDIM];
__device__ __align__(16) __half g_WpfbT[(size_t)BATCH * TDIM * HDIM];
__device__ float g_Wpf[HDIM * TDIM];
__device__ float g_cpf[TDIM];
__device__ float g_Gacc[BATCH * HDIM];
__device__ float g_S[BATCH];

// ---------------------------- helpers --------------------------------------
__device__ __forceinline__ uint32_t smem_u32(const void* p) {
    uint32_t a;
    asm("{ .reg .u64 t; cvta.to.shared.u64 t, %1; cvt.u32.u64 %0, t; }" : "=r"(a) : "l"(p));
    return a;
}

#define CP_ASYNC16(dst, src) \
    asm volatile("cp.async.cg.shared.global [%0], [%1], 16;" :: "r"(dst), "l"(src) : "memory")
#define CP_COMMIT() asm volatile("cp.async.commit_group;" ::: "memory")
#define CP_WAIT1()  asm volatile("cp.async.wait_group 1;" ::: "memory")

__device__ __forceinline__ void mma_f16(float c[4], const uint32_t a[4], const uint32_t b[2]) {
    asm volatile(
        "mma.sync.aligned.m16n8k16.row.col.f32.f16.f16.f32 "
        "{%0,%1,%2,%3}, {%4,%5,%6,%7}, {%8,%9}, {%0,%1,%2,%3};\n"
        : "+f"(c[0]), "+f"(c[1]), "+f"(c[2]), "+f"(c[3])
        : "r"(a[0]), "r"(a[1]), "r"(a[2]), "r"(a[3]), "r"(b[0]), "r"(b[1]));
}

__device__ __forceinline__ void ldsm4(uint32_t& r0, uint32_t& r1, uint32_t& r2, uint32_t& r3,
                                      uint32_t addr) {
    asm volatile("ldmatrix.sync.aligned.m8n8.x4.shared.b16 {%0,%1,%2,%3}, [%4];"
                 : "=r"(r0), "=r"(r1), "=r"(r2), "=r"(r3) : "r"(addr));
}

// stage geometry: BK=64; A tile 128x64 and W tile 128x64, both padded ld=72
#define LDT 72
#define A_BYTES (128 * LDT * 2)
#define W_BYTES (128 * LDT * 2)
#define STAGE_BYTES (A_BYTES + W_BYTES)
#define NSTG 3
#define SMEM_DYN (NSTG * STAGE_BYTES)

__device__ __forceinline__ void load_tile(uint32_t stA, const __half* __restrict__ A,
                                          const __half* __restrict__ Wt,
                                          int r0, int n0, int k0, int tid) {
    uint32_t stW = stA + A_BYTES;
#pragma unroll
    for (int it = 0; it < 4; ++it) {
        int u = tid + it * 256;
        int row = u >> 3, c = u & 7;
        CP_ASYNC16(stA + (uint32_t)(row * LDT * 2 + c * 16),
                   A + (size_t)(r0 + row) * HDIM + k0 + c * 8);
    }
#pragma unroll
    for (int it = 0; it < 4; ++it) {
        int u = tid + it * 256;
        int row = u >> 3, c = u & 7;
        CP_ASYNC16(stW + (uint32_t)(row * LDT * 2 + c * 16),
                   Wt + (size_t)(n0 + row) * HDIM + k0 + c * 8);
    }
}

// BK=64 chunk as 16 (ks,mf) steps; af double-buffered per step, bw per ks.
__device__ __forceinline__ void compute_chunk(uint32_t aBase, uint32_t bBase,
                                              float acc[4][4][4]) {
    uint32_t af[2][4];
    uint32_t bw[2][4][2];
    ldsm4(bw[0][0][0], bw[0][0][1], bw[0][1][0], bw[0][1][1], bBase);
    ldsm4(bw[0][2][0], bw[0][2][1], bw[0][3][0], bw[0][3][1],
          bBase + (uint32_t)(16 * LDT * 2));
    ldsm4(af[0][0], af[0][1], af[0][2], af[0][3], aBase);
#pragma unroll
    for (int s = 0; s < 16; ++s) {
        const int ks = s >> 2, mf = s & 3;
        if (s + 1 < 16) {
            const int nks = (s + 1) >> 2, nmf = (s + 1) & 3;
            ldsm4(af[(s + 1) & 1][0], af[(s + 1) & 1][1],
                  af[(s + 1) & 1][2], af[(s + 1) & 1][3],
                  aBase + (uint32_t)((nmf * 16 * LDT + nks * 16) * 2));
        }
        if (mf == 2 && ks < 3) {
            const int nb = (ks + 1) & 1;
            ldsm4(bw[nb][0][0], bw[nb][0][1], bw[nb][1][0], bw[nb][1][1],
                  bBase + (uint32_t)(((ks + 1) * 16) * 2));
            ldsm4(bw[nb][2][0], bw[nb][2][1], bw[nb][3][0], bw[nb][3][1],
                  bBase + (uint32_t)((16 * LDT + (ks + 1) * 16) * 2));
        }
#pragma unroll
        for (int nf = 0; nf < 4; ++nf)
            mma_f16(acc[mf][nf], af[s & 1], bw[ks & 1][nf]);
    }
}

// ---------------------------------------------------------------------------
__global__ void conv_x_kernel(const float* __restrict__ x) {
    size_t gtid = blockIdx.x * blockDim.x + threadIdx.x;
    if (gtid < BATCH * HDIM) g_Gacc[gtid] = 0.0f;
    if (gtid < BATCH) g_S[gtid] = 0.0f;
    size_t n4 = (size_t)MTOT * HDIM / 4;
    __half2* dst = reinterpret_cast<__half2*>(g_Xh);
    for (size_t i = gtid; i < n4; i += (size_t)gridDim.x * blockDim.x) {
        float4 v = reinterpret_cast<const float4*>(x)[i];
        dst[2 * i]     = __floats2half2_rn(v.x, v.y);
        dst[2 * i + 1] = __floats2half2_rn(v.z, v.w);
    }
}

__global__ void transpose_all_kernel(const float* __restrict__ Wq,
                                     const float* __restrict__ Wk,
                                     const float* __restrict__ Wf) {
    const int z = blockIdx.z;
    const float* src = (z == 0) ? Wq : (z == 1) ? Wk : Wf;
    __half* dst = (z == 0) ? g_WqT : (z == 1) ? g_WkT : g_WfT;
    const int cols = (z == 2) ? TDIM : HDIM;
    if (blockIdx.x * 32 >= cols) return;
    __shared__ float t[32][33];
    int x0 = blockIdx.x * 32, y0 = blockIdx.y * 32;
    int tx = threadIdx.x, ty = threadIdx.y;
#pragma unroll
    for (int i = 0; i < 4; ++i)
        t[ty + 8 * i][tx] = src[(size_t)(y0 + ty + 8 * i) * cols + x0 + tx];
    __syncthreads();
#pragma unroll
    for (int i = 0; i < 4; ++i)
        dst[(size_t)(x0 + ty + 8 * i) * HDIM + y0 + tx] = __float2half_rn(t[tx][ty + 8 * i]);
}

__global__ void prep_kernel(const float* __restrict__ Wp, const float* __restrict__ Wf,
                            const float* __restrict__ bp, const float* __restrict__ bf) {
    int j = threadIdx.x;
    if (blockIdx.x < 32) {
        __shared__ float Wp_s[16][512];
        int i0 = blockIdx.x * 16;
        for (int i = threadIdx.x; i < 16 * 512; i += 256)
            Wp_s[i >> 9][i & 511] = Wp[(size_t)(i0 + (i >> 9)) * 512 + (i & 511)];
        __syncthreads();
        float acc[16];
#pragma unroll
        for (int i = 0; i < 16; ++i) acc[i] = 0.0f;
        for (int k = 0; k < 512; ++k) {
            float wf = Wf[(size_t)k * TDIM + j];
#pragma unroll
            for (int i = 0; i < 16; ++i) acc[i] += Wp_s[i][k] * wf;
        }
#pragma unroll
        for (int i = 0; i < 16; ++i) g_Wpf[(size_t)(i0 + i) * TDIM + j] = acc[i];
    } else {
        __shared__ float bp_s[512];
        for (int i = threadIdx.x; i < 512; i += 256) bp_s[i] = bp[i];
        __syncthreads();
        float a = bf[j];
        for (int k = 0; k < 512; ++k) a += bp_s[k] * Wf[(size_t)k * TDIM + j];
        g_cpf[j] = a;
    }
}

__global__ void build_wpfbt_kernel() {
    int n = blockIdx.x, b = blockIdx.y, k = threadIdx.x;
    float denom = fmaxf(SCALE_F * sqrtf(g_S[b]), EPS_F);
    float gk = SCALE_F * g_Gacc[b * HDIM + k] / denom;
    g_WpfbT[((size_t)b * TDIM + n) * HDIM + k] =
        __float2half_rn(gk * g_Wpf[(size_t)k * TDIM + n]);
}

__global__ void rowwise_kernel(const float* __restrict__ wg) {
    __shared__ float wg_s[512];
    __shared__ float Gs[8][512];
    __shared__ float Sq[8];
    const int tid = threadIdx.x, warp = tid >> 5, lane = tid & 31;
    const int r0 = blockIdx.x * 128;
    const int b = r0 >> 12;

    for (int i = tid; i < 512; i += 256) wg_s[i] = wg[i];
    for (int i = tid; i < 8 * 512; i += 256) (&Gs[0][0])[i] = 0.0f;
    __syncthreads();

    float qw2 = 0.0f;
    for (int rt = 0; rt < 16; ++rt) {
        int r = r0 + rt * 8 + warp;
        const __half2* qr = reinterpret_cast<const __half2*>(g_Qh + (size_t)r * HDIM);
        __half2* kr = reinterpret_cast<__half2*>(g_Kh + (size_t)r * HDIM);
        float2 q[8], k[8];
        float sq = 0.0f, sg = 0.0f, sk = 0.0f;
#pragma unroll
        for (int t = 0; t < 8; ++t) {
            int j2 = lane + 32 * t;
            q[t] = __half22float2(qr[j2]);
            k[t] = __half22float2(kr[j2]);
            sq += q[t].x * q[t].x + q[t].y * q[t].y;
            sk += k[t].x * k[t].x + k[t].y * k[t].y;
            sg += q[t].x * wg_s[2 * j2] + q[t].y * wg_s[2 * j2 + 1];
        }
#pragma unroll
        for (int o = 16; o; o >>= 1) {
            sq += __shfl_xor_sync(0xffffffffu, sq, o);
            sg += __shfl_xor_sync(0xffffffffu, sg, o);
            sk += __shfl_xor_sync(0xffffffffu, sk, o);
        }
        float dq = fmaxf(sqrtf(sq), EPS_F);
        float dk = fmaxf(sqrtf(sk), EPS_F);
        float qw = sg / dq;
        float rk = 1.0f / dk;
        qw2 += qw * qw;
#pragma unroll
        for (int t = 0; t < 8; ++t) {
            int j2 = lane + 32 * t;
            kr[j2] = __floats2half2_rn(k[t].x * rk, k[t].y * rk);
            Gs[warp][2 * j2]     += qw * q[t].x;
            Gs[warp][2 * j2 + 1] += qw * q[t].y;
        }
    }
    if (lane == 0) Sq[warp] = qw2;
    __syncthreads();

    for (int j = tid; j < 512; j += 256) {
        float s = 0.0f;
#pragma unroll
        for (int w = 0; w < 8; ++w) s += Gs[w][j];
        atomicAdd(&g_Gacc[b * HDIM + j], s);
    }
    if (tid == 0) {
        float s = 0.0f;
#pragma unroll
        for (int w = 0; w < 8; ++w) s += Sq[w];
        atomicAdd(&g_S[b], s);
    }
}

// ---------------------------------------------------------------------------
__global__ __launch_bounds__(256, 2)
void qk_gemm_kernel(const float* __restrict__ bq, const float* __restrict__ bk) {
    extern __shared__ char sm_raw[];
    const int bx = blockIdx.x;
    const bool isQ = (bx < 4);
    const __half* Wt = isQ ? g_WqT : g_WkT;
    const float* bias = isQ ? bq : bk;
    __half* C = isQ ? g_Qh : g_Kh;
    const int n0 = (bx & 3) * 128;
    const int r0 = blockIdx.y * 128;
    const int tid = threadIdx.x, warp = tid >> 5, lane = tid & 31;
    const int wm = warp >> 2, wn = warp & 3, g = lane >> 2, tg = lane & 3;

    uint32_t smBase = smem_u32(sm_raw);
    const uint32_t aOff = (uint32_t)(((wm * 64 + (lane & 15)) * LDT + ((lane >> 4) * 8)) * 2);
    const uint32_t bOff = (uint32_t)(A_BYTES +
        ((wn * 32 + ((lane >> 4) * 8) + (lane & 7)) * LDT + (((lane >> 3) & 1) * 8)) * 2);

    float acc[4][4][4];
#pragma unroll
    for (int a = 0; a < 4; ++a)
#pragma unroll
        for (int b2 = 0; b2 < 4; ++b2)
#pragma unroll
            for (int c = 0; c < 4; ++c) acc[a][b2][c] = 0.0f;

    load_tile(smBase + 0 * STAGE_BYTES, g_Xh, Wt, r0, n0, 0, tid);  CP_COMMIT();
    load_tile(smBase + 1 * STAGE_BYTES, g_Xh, Wt, r0, n0, 64, tid); CP_COMMIT();

    const int TOT = 8;
    for (int c = 0; c < TOT; ++c) {
        CP_WAIT1();
        __syncthreads();
        if (c + 2 < TOT) {
            load_tile(smBase + (uint32_t)((c + 2) % NSTG) * STAGE_BYTES, g_Xh, Wt,
                      r0, n0, (c + 2) * 64, tid);
            CP_COMMIT();
        }
        uint32_t stage = smBase + (uint32_t)(c % NSTG) * STAGE_BYTES;
        compute_chunk(stage + aOff, stage + bOff, acc);
    }

#pragma unroll
    for (int mf = 0; mf < 4; ++mf) {
#pragma unroll
        for (int nf = 0; nf < 4; ++nf) {
            int row = r0 + wm * 64 + mf * 16 + g;
            int col = n0 + wn * 32 + nf * 8 + tg * 2;
            float b0v = bias[col], b1v = bias[col + 1];
            *reinterpret_cast<__half2*>(&C[(size_t)row * HDIM + col]) =
                __floats2half2_rn(acc[mf][nf][0] + b0v, acc[mf][nf][1] + b1v);
            *reinterpret_cast<__half2*>(&C[(size_t)(row + 8) * HDIM + col]) =
                __floats2half2_rn(acc[mf][nf][2] + b0v, acc[mf][nf][3] + b1v);
        }
    }
}

// ---------------------------------------------------------------------------
__global__ __launch_bounds__(256, 2)
void final_gemm_kernel(float* __restrict__ out) {
    extern __shared__ char sm_raw[];
    const int n0 = blockIdx.x * 128;
    const int r0 = blockIdx.y * 128;
    const int batch = r0 >> 12;
    const __half* W1 = g_WpfbT + (size_t)batch * TDIM * HDIM;
    const int tid = threadIdx.x, warp = tid >> 5, lane = tid & 31;
    const int wm = warp >> 2, wn = warp & 3, g = lane >> 2, tg = lane & 3;

    uint32_t smBase = smem_u32(sm_raw);
    const uint32_t aOff = (uint32_t)(((wm * 64 + (lane & 15)) * LDT + ((lane >> 4) * 8)) * 2);
    const uint32_t bOff = (uint32_t)(A_BYTES +
        ((wn * 32 + ((lane >> 4) * 8) + (lane & 7)) * LDT + (((lane >> 3) & 1) * 8)) * 2);

    float acc[4][4][4];
#pragma unroll
    for (int a = 0; a < 4; ++a)
#pragma unroll
        for (int b2 = 0; b2 < 4; ++b2)
#pragma unroll
            for (int c = 0; c < 4; ++c) acc[a][b2][c] = 0.0f;

    auto issue = [&](int c) {
        int pass = c >> 3, k0 = (c & 7) * 64;
        load_tile(smBase + (uint32_t)(c % NSTG) * STAGE_BYTES,
                  pass ? g_Kh : g_Qh, pass ? W1 : g_WfT, r0, n0, k0, tid);
    };

    issue(0); CP_COMMIT();
    issue(1); CP_COMMIT();

    const int TOT = 16;
    for (int c = 0; c < TOT; ++c) {
        CP_WAIT1();
        __syncthreads();
        if (c + 2 < TOT) { issue(c + 2); CP_COMMIT(); }
        uint32_t stage = smBase + (uint32_t)(c % NSTG) * STAGE_BYTES;
        compute_chunk(stage + aOff, stage + bOff, acc);
    }

#pragma unroll
    for (int mf = 0; mf < 4; ++mf) {
#pragma unroll
        for (int nf = 0; nf < 4; ++nf) {
            int row = r0 + wm * 64 + mf * 16 + g;
            int col = n0 + wn * 32 + nf * 8 + tg * 2;
            float b0v = g_cpf[col], b1v = g_cpf[col + 1];
            *reinterpret_cast<float2*>(&out[(size_t)row * TDIM + col]) =
                make_float2(acc[mf][nf][0] + b0v, acc[mf][nf][1] + b1v);
            *reinterpret_cast<float2*>(&out[(size_t)(row + 8) * TDIM + col]) =
                make_float2(acc[mf][nf][2] + b0v, acc[mf][nf][3] + b1v);
        }
    }
}

// ---------------------------------------------------------------------------
extern "C" void kernel_launch(void* const* d_in, const int* in_sizes, int n_in,
                              void* d_out, int out_size) {
    const float* x  = (const float*)d_in[0];
    const float* Wq = (const float*)d_in[1];
    const float* bq = (const float*)d_in[2];
    const float* Wk = (const float*)d_in[3];
    const float* bk = (const float*)d_in[4];
    const float* wg = (const float*)d_in[5];
    const float* Wp = (const float*)d_in[6];
    const float* bp = (const float*)d_in[7];
    const float* Wf = (const float*)d_in[8];
    const float* bf = (const float*)d_in[9];
    float* out = (float*)d_out;

    cudaFuncSetAttribute(qk_gemm_kernel, cudaFuncAttributeMaxDynamicSharedMemorySize, SMEM_DYN);
    cudaFuncSetAttribute(final_gemm_kernel, cudaFuncAttributeMaxDynamicSharedMemorySize, SMEM_DYN);

    conv_x_kernel<<<2048, 256>>>(x);                                        // 1
    transpose_all_kernel<<<dim3(16, 16, 3), dim3(32, 8)>>>(Wq, Wk, Wf);     // 2
    prep_kernel<<<33, 256>>>(Wp, Wf, bp, bf);                               // 3
    qk_gemm_kernel<<<dim3(8, 512), 256, SMEM_DYN>>>(bq, bk);                // 4 <- ncu slot
    rowwise_kernel<<<512, 256>>>(wg);                                       // 5
    build_wpfbt_kernel<<<dim3(256, 16), 512>>>();                           // 6
    final_gemm_kernel<<<dim3(2, 512), 256, SMEM_DYN>>>(out);                // 7
}